// round 3
// baseline (speedup 1.0000x reference)
#include <cuda_runtime.h>
#include <cuda_bf16.h>
#include <math.h>

// ---------------------------------------------------------------------------
// Problem constants: B=4, S=2048, E=2048, H=16, D=128
// ---------------------------------------------------------------------------
#define BB   4
#define SS   2048
#define EE   2048
#define HH   16
#define DD   128
#define MM   (BB * SS)        // 8192 rows
#define QKVN (3 * EE)         // 6144

// ---------------------------------------------------------------------------
// Scratch (device globals -- allocation-free rule). 268 MB total.
// q/k/v in [B,H,S,D]; y (attention out) in [B,S,E].
// ---------------------------------------------------------------------------
__device__ float g_q[(size_t)BB * HH * SS * DD];    // 67 MB
__device__ float g_k[(size_t)BB * HH * SS * DD];
__device__ float g_v[(size_t)BB * HH * SS * DD];
__device__ float g_y[(size_t)MM * EE];              // 67 MB

// ---------------------------------------------------------------------------
// SGEMM core: 128x128 block tile, K-step 8, 8x8 per thread, 256 threads,
// double-buffered smem. M,N multiples of 128; K multiple of 8.
// SPLIT_QKV=0: C[M,N] row-major.
// SPLIT_QKV=1: N=6144 QKV output scattered directly into q/k/v [B,H,S,D].
// ---------------------------------------------------------------------------
template <int SPLIT_QKV>
__global__ __launch_bounds__(256, 2)
void sgemm128(const float* __restrict__ A, const float* __restrict__ B,
              float* __restrict__ C0, float* __restrict__ C1,
              float* __restrict__ C2, int M, int N, int K)
{
    __shared__ float As[2][8][132];   // transposed A tile, padded for bank spread
    __shared__ float Bs[2][8][128];

    const int tid = threadIdx.x;
    const int bm0 = blockIdx.y * 128;
    const int bn0 = blockIdx.x * 128;
    const int tx  = tid & 15;
    const int ty  = tid >> 4;

    // A tile loader: 128 rows x 8 cols, one float4 per thread
    const int arow = tid >> 1;
    const int acol = (tid & 1) * 4;
    const float* Ag = A + (size_t)(bm0 + arow) * K + acol;

    // B tile loader: 8 rows x 128 cols, one float4 per thread
    const int brow = tid >> 5;
    const int bcol = (tid & 31) * 4;
    const float* Bg = B + (size_t)brow * N + bn0 + bcol;

    // preload tile 0
    float4 a_reg = *(const float4*)Ag;
    float4 b_reg = *(const float4*)Bg;
    As[0][acol + 0][arow] = a_reg.x;
    As[0][acol + 1][arow] = a_reg.y;
    As[0][acol + 2][arow] = a_reg.z;
    As[0][acol + 3][arow] = a_reg.w;
    *(float4*)&Bs[0][brow][bcol] = b_reg;
    __syncthreads();

    float acc[8][8];
    #pragma unroll
    for (int i = 0; i < 8; i++)
        #pragma unroll
        for (int j = 0; j < 8; j++) acc[i][j] = 0.0f;

    const int ntiles = K >> 3;
    for (int t = 0; t < ntiles; t++) {
        const int buf = t & 1;
        if (t + 1 < ntiles) {
            a_reg = *(const float4*)(Ag + (t + 1) * 8);
            b_reg = *(const float4*)(Bg + (size_t)(t + 1) * 8 * N);
        }
        #pragma unroll
        for (int k = 0; k < 8; k++) {
            float af[8], bf[8];
            *(float4*)&af[0] = *(float4*)&As[buf][k][ty * 8];
            *(float4*)&af[4] = *(float4*)&As[buf][k][ty * 8 + 4];
            *(float4*)&bf[0] = *(float4*)&Bs[buf][k][tx * 8];
            *(float4*)&bf[4] = *(float4*)&Bs[buf][k][tx * 8 + 4];
            #pragma unroll
            for (int i = 0; i < 8; i++)
                #pragma unroll
                for (int j = 0; j < 8; j++)
                    acc[i][j] = fmaf(af[i], bf[j], acc[i][j]);
        }
        if (t + 1 < ntiles) {
            const int nb = buf ^ 1;
            As[nb][acol + 0][arow] = a_reg.x;
            As[nb][acol + 1][arow] = a_reg.y;
            As[nb][acol + 2][arow] = a_reg.z;
            As[nb][acol + 3][arow] = a_reg.w;
            *(float4*)&Bs[nb][brow][bcol] = b_reg;
        }
        __syncthreads();
    }

    if (SPLIT_QKV) {
        // Tile columns bn0..bn0+127 lie entirely in one (q/k/v, head) slice:
        // which = bn0/2048, h = (bn0%2048)/128; d spans 0..127.
        // Rows bm0..bm0+127 lie within one b (S=2048 is a multiple of 128).
        const int which = bn0 >> 11;
        const int h     = (bn0 & 2047) >> 7;
        const int b     = bm0 >> 11;
        const int s0    = bm0 & 2047;
        float* dstb = (which == 0 ? C0 : (which == 1 ? C1 : C2))
                      + ((size_t)(b * HH + h) * SS) * DD;
        #pragma unroll
        for (int i = 0; i < 8; i++) {
            float* Cp = dstb + (size_t)(s0 + ty * 8 + i) * DD + tx * 8;
            *(float4*)Cp       = make_float4(acc[i][0], acc[i][1], acc[i][2], acc[i][3]);
            *(float4*)(Cp + 4) = make_float4(acc[i][4], acc[i][5], acc[i][6], acc[i][7]);
        }
    } else {
        #pragma unroll
        for (int i = 0; i < 8; i++) {
            float* Cp = C0 + (size_t)(bm0 + ty * 8 + i) * N + bn0 + tx * 8;
            *(float4*)Cp       = make_float4(acc[i][0], acc[i][1], acc[i][2], acc[i][3]);
            *(float4*)(Cp + 4) = make_float4(acc[i][4], acc[i][5], acc[i][6], acc[i][7]);
        }
    }
}

// ---------------------------------------------------------------------------
// RoPE + QK-RMSNorm, in-place on q,k in [B,H,S,D] layout (v untouched).
// One 64-thread block per (b,s,h); thread j handles pair (2j, 2j+1).
// ---------------------------------------------------------------------------
__global__ __launch_bounds__(64)
void rope_norm(float* __restrict__ q, float* __restrict__ k)
{
    const int h = blockIdx.x;
    const int s = blockIdx.y;
    const int b = blockIdx.z;
    const int j = threadIdx.x;          // pair index 0..63

    const size_t base = ((size_t)((b * HH + h) * SS + s)) * DD + 2 * j;
    const float2 qp = *(const float2*)(q + base);
    const float2 kp = *(const float2*)(k + base);

    // inv_freq = 1 / 10000^{(2j)/128}; freqs = s * inv_freq (all fp32 like ref)
    const float ex   = (float)(2 * j) * (1.0f / (float)DD);
    const float invf = 1.0f / powf(10000.0f, ex);
    const float fr   = (float)s * invf;
    float sn, cs;
    sincosf(fr, &sn, &cs);

    const float q0 = qp.x * cs - qp.y * sn;
    const float q1 = qp.x * sn + qp.y * cs;
    const float k0 = kp.x * cs - kp.y * sn;
    const float k1 = kp.x * sn + kp.y * cs;

    float sq = q0 * q0 + q1 * q1;
    float sk = k0 * k0 + k1 * k1;
    #pragma unroll
    for (int off = 16; off; off >>= 1) {
        sq += __shfl_xor_sync(0xffffffffu, sq, off);
        sk += __shfl_xor_sync(0xffffffffu, sk, off);
    }
    __shared__ float sh[4];
    if ((j & 31) == 0) { sh[(j >> 5) * 2] = sq; sh[(j >> 5) * 2 + 1] = sk; }
    __syncthreads();
    const float tq = sh[0] + sh[2];
    const float tk = sh[1] + sh[3];
    const float rq = rsqrtf(tq * (1.0f / (float)DD) + 1e-5f);
    const float rk = rsqrtf(tk * (1.0f / (float)DD) + 1e-5f);

    *(float2*)(q + base) = make_float2(q0 * rq, q1 * rq);
    *(float2*)(k + base) = make_float2(k0 * rk, k1 * rk);
}

// ---------------------------------------------------------------------------
// Causal flash attention, fp32, online softmax.
// Grid: (S/64, B*H). 256 threads = 16x16; 4x4 score microtile, 4x8 O microtile.
// Writes y directly in [B, S, H*D] layout (proj GEMM input).
// ---------------------------------------------------------------------------
#define QS_STRIDE 68   // 64 + 4 pad
#define PS_STRIDE 65
#define FLASH_SMEM_FLOATS (DD * QS_STRIDE * 2 + 64 * DD + 64 * PS_STRIDE)
#define FLASH_SMEM_BYTES  (FLASH_SMEM_FLOATS * 4)

__global__ __launch_bounds__(256)
void flash_attn(const float* __restrict__ Qg, const float* __restrict__ Kg,
                const float* __restrict__ Vg, float* __restrict__ Yg)
{
    const int bh  = blockIdx.y;
    const int qt  = blockIdx.x;
    const int qm0 = qt * 64;
    const int b   = bh >> 4;      // H = 16
    const int h   = bh & 15;

    extern __shared__ float sm[];
    float* Qs = sm;                      // [128][68], transposed: Qs[d][i]
    float* Ks = Qs + DD * QS_STRIDE;     // [128][68], transposed: Ks[d][j]
    float* Vs = Ks + DD * QS_STRIDE;     // [64][128], row-major
    float* Ps = Vs + 64 * DD;            // [64][65]

    const int tid = threadIdx.x;
    const int tx  = tid & 15;
    const int ty  = tid >> 4;

    const float* Qb = Qg + (size_t)bh * SS * DD;
    const float* Kb = Kg + (size_t)bh * SS * DD;
    const float* Vb = Vg + (size_t)bh * SS * DD;

    // Load Q tile transposed into smem
    for (int e = tid; e < 64 * 32; e += 256) {
        const int i  = e >> 5;
        const int d4 = (e & 31) << 2;
        float4 v = *(const float4*)(Qb + (size_t)(qm0 + i) * DD + d4);
        Qs[(d4 + 0) * QS_STRIDE + i] = v.x;
        Qs[(d4 + 1) * QS_STRIDE + i] = v.y;
        Qs[(d4 + 2) * QS_STRIDE + i] = v.z;
        Qs[(d4 + 3) * QS_STRIDE + i] = v.w;
    }

    float o[4][8];
    float m[4], l[4];
    #pragma unroll
    for (int ii = 0; ii < 4; ii++) {
        m[ii] = -1e30f; l[ii] = 0.0f;
        #pragma unroll
        for (int c = 0; c < 8; c++) o[ii][c] = 0.0f;
    }
    const float scale = 0.08838834764831845f;   // 1/sqrt(128)

    for (int kt = 0; kt <= qt; kt++) {
        const int kn0 = kt * 64;
        __syncthreads();   // prior iter done with Ks/Vs (covers Q stores on kt=0)

        for (int e = tid; e < 64 * 32; e += 256) {
            const int j  = e >> 5;
            const int d4 = (e & 31) << 2;
            float4 kv = *(const float4*)(Kb + (size_t)(kn0 + j) * DD + d4);
            Ks[(d4 + 0) * QS_STRIDE + j] = kv.x;
            Ks[(d4 + 1) * QS_STRIDE + j] = kv.y;
            Ks[(d4 + 2) * QS_STRIDE + j] = kv.z;
            Ks[(d4 + 3) * QS_STRIDE + j] = kv.w;
            *(float4*)&Vs[j * DD + d4] = *(const float4*)(Vb + (size_t)(kn0 + j) * DD + d4);
        }
        __syncthreads();

        // S = Q K^T (4x4 per thread)
        float s[4][4];
        #pragma unroll
        for (int ii = 0; ii < 4; ii++)
            #pragma unroll
            for (int jj = 0; jj < 4; jj++) s[ii][jj] = 0.0f;

        #pragma unroll 8
        for (int d = 0; d < DD; d++) {
            float4 aq = *(float4*)&Qs[d * QS_STRIDE + ty * 4];
            float4 bk = *(float4*)&Ks[d * QS_STRIDE + tx * 4];
            const float a[4]  = {aq.x, aq.y, aq.z, aq.w};
            const float bb[4] = {bk.x, bk.y, bk.z, bk.w};
            #pragma unroll
            for (int ii = 0; ii < 4; ii++)
                #pragma unroll
                for (int jj = 0; jj < 4; jj++)
                    s[ii][jj] = fmaf(a[ii], bb[jj], s[ii][jj]);
        }

        #pragma unroll
        for (int ii = 0; ii < 4; ii++)
            #pragma unroll
            for (int jj = 0; jj < 4; jj++)
                s[ii][jj] *= scale;
        if (kt == qt) {
            #pragma unroll
            for (int ii = 0; ii < 4; ii++) {
                const int ig = ty * 4 + ii;
                #pragma unroll
                for (int jj = 0; jj < 4; jj++)
                    if (tx * 4 + jj > ig) s[ii][jj] = -1e30f;
            }
        }

        // Online softmax update (16 lanes share a row group)
        #pragma unroll
        for (int ii = 0; ii < 4; ii++) {
            float mx = fmaxf(fmaxf(s[ii][0], s[ii][1]), fmaxf(s[ii][2], s[ii][3]));
            #pragma unroll
            for (int off = 1; off < 16; off <<= 1)
                mx = fmaxf(mx, __shfl_xor_sync(0xffffffffu, mx, off));
            const float nm   = fmaxf(m[ii], mx);
            const float corr = __expf(m[ii] - nm);
            float rs = 0.0f;
            #pragma unroll
            for (int jj = 0; jj < 4; jj++) {
                const float p = __expf(s[ii][jj] - nm);
                s[ii][jj] = p;
                rs += p;
            }
            #pragma unroll
            for (int off = 1; off < 16; off <<= 1)
                rs += __shfl_xor_sync(0xffffffffu, rs, off);
            l[ii] = l[ii] * corr + rs;
            m[ii] = nm;
            #pragma unroll
            for (int c = 0; c < 8; c++) o[ii][c] *= corr;
            #pragma unroll
            for (int jj = 0; jj < 4; jj++)
                Ps[(ty * 4 + ii) * PS_STRIDE + tx * 4 + jj] = s[ii][jj];
        }
        __syncthreads();

        // O += P @ V
        #pragma unroll 4
        for (int j = 0; j < 64; j++) {
            float4 b0 = *(float4*)&Vs[j * DD + tx * 8];
            float4 b1 = *(float4*)&Vs[j * DD + tx * 8 + 4];
            float a[4];
            #pragma unroll
            for (int ii = 0; ii < 4; ii++) a[ii] = Ps[(ty * 4 + ii) * PS_STRIDE + j];
            #pragma unroll
            for (int ii = 0; ii < 4; ii++) {
                o[ii][0] = fmaf(a[ii], b0.x, o[ii][0]);
                o[ii][1] = fmaf(a[ii], b0.y, o[ii][1]);
                o[ii][2] = fmaf(a[ii], b0.z, o[ii][2]);
                o[ii][3] = fmaf(a[ii], b0.w, o[ii][3]);
                o[ii][4] = fmaf(a[ii], b1.x, o[ii][4]);
                o[ii][5] = fmaf(a[ii], b1.y, o[ii][5]);
                o[ii][6] = fmaf(a[ii], b1.z, o[ii][6]);
                o[ii][7] = fmaf(a[ii], b1.w, o[ii][7]);
            }
        }
    }

    // Normalize and write y in [B, S, E] layout (col = h*128 + d)
    #pragma unroll
    for (int ii = 0; ii < 4; ii++) {
        const float invl = 1.0f / l[ii];
        const int ig = qm0 + ty * 4 + ii;
        float* yp = Yg + ((size_t)(b * SS + ig)) * EE + h * DD + tx * 8;
        *(float4*)yp       = make_float4(o[ii][0] * invl, o[ii][1] * invl,
                                         o[ii][2] * invl, o[ii][3] * invl);
        *(float4*)(yp + 4) = make_float4(o[ii][4] * invl, o[ii][5] * invl,
                                         o[ii][6] * invl, o[ii][7] * invl);
    }
}

// ---------------------------------------------------------------------------
// Launch
// ---------------------------------------------------------------------------
extern "C" void kernel_launch(void* const* d_in, const int* in_sizes, int n_in,
                              void* d_out, int out_size)
{
    const float* x      = (const float*)d_in[0];
    const float* w_qkv  = (const float*)d_in[1];
    const float* w_proj = (const float*)d_in[2];
    float* out          = (float*)d_out;

    float *q_p, *k_p, *v_p, *y_p;
    cudaGetSymbolAddress((void**)&q_p, g_q);
    cudaGetSymbolAddress((void**)&k_p, g_k);
    cudaGetSymbolAddress((void**)&v_p, g_v);
    cudaGetSymbolAddress((void**)&y_p, g_y);

    cudaFuncSetAttribute(flash_attn, cudaFuncAttributeMaxDynamicSharedMemorySize,
                         FLASH_SMEM_BYTES);

    // 1) QKV projection with fused head-split: [8192,2048] @ [2048,6144]
    sgemm128<1><<<dim3(QKVN / 128, MM / 128), 256>>>(x, w_qkv, q_p, k_p, v_p,
                                                     MM, QKVN, EE);

    // 2) RoPE + RMSNorm in-place on q,k
    rope_norm<<<dim3(HH, SS, BB), 64>>>(q_p, k_p);

    // 3) Causal flash attention
    flash_attn<<<dim3(SS / 64, BB * HH), 256, FLASH_SMEM_BYTES>>>(q_p, k_p, v_p, y_p);

    // 4) Output projection: [8192,2048] @ [2048,2048] -> d_out
    sgemm128<0><<<dim3(EE / 128, MM / 128), 256>>>(y_p, w_proj, out, nullptr, nullptr,
                                                   MM, EE, EE);
}

// round 9
// speedup vs baseline: 1.3081x; 1.3081x over previous
#include <cuda_runtime.h>
#include <cuda_bf16.h>
#include <mma.h>
#include <math.h>
#include <stdint.h>

using namespace nvcuda;

// ---------------------------------------------------------------------------
// Problem constants: B=4, S=2048, E=2048, H=16, D=128
// ---------------------------------------------------------------------------
#define BB   4
#define SS   2048
#define EE   2048
#define HH   16
#define DD   128
#define MM   (BB * SS)        // 8192 rows
#define QKVN (3 * EE)         // 6144

// ---------------------------------------------------------------------------
// Scratch (device globals -- allocation-free rule). 268 MB total.
// ---------------------------------------------------------------------------
__device__ float g_q[(size_t)BB * HH * SS * DD];    // 67 MB, [B,H,S,D]
__device__ float g_k[(size_t)BB * HH * SS * DD];
__device__ float g_v[(size_t)BB * HH * SS * DD];
__device__ float g_y[(size_t)MM * EE];              // 67 MB, [B,S,E]

// ---------------------------------------------------------------------------
// Software tf32 rounding (round-to-nearest to 10 mantissa bits) -- pure
// integer ops, no inline asm, no intrinsic version sensitivity.
// ---------------------------------------------------------------------------
__device__ __forceinline__ float f2tf32f(float x) {
    uint32_t u = __float_as_uint(x);
    u += 0x1000u;              // round at bit 13 (ties up)
    u &= 0xFFFFE000u;          // clear dropped mantissa bits
    return __uint_as_float(u);
}

// ---------------------------------------------------------------------------
// tf32 tensor-core GEMM via nvcuda::wmma (m16n16k8) -- NO inline asm.
// C[M,N] = A[M,K] @ B[K,N], fp32 in/out.
// 128x128 block tile, k-step 16 (two k8 sub-steps), double-buffered smem.
// 256 threads = 8 warps in 2(m) x 4(n); warp tile 64x32 = 4x2 wmma tiles.
// tf32 rounding applied once at the global->smem stage.
// SPLIT_QKV=1: output tiles map contiguously into q/k/v [B,H,S,D] slices.
// ---------------------------------------------------------------------------
#define KSTEP 16
#define SSTR  136   // padded stride; multiple of 8 floats (wmma ldm rule)

template <int SPLIT_QKV>
__global__ __launch_bounds__(256, 2)
void gemm_tf32(const float* __restrict__ A, const float* __restrict__ B,
               float* __restrict__ C0, float* __restrict__ C1,
               float* __restrict__ C2, int M, int N, int K)
{
    __shared__ float As[2][KSTEP][SSTR];   // [k][m]  (A transposed -> col_major A)
    __shared__ float Bs[2][KSTEP][SSTR];   // [k][n]  (row_major B)

    const int tid  = threadIdx.x;
    const int wid  = tid >> 5;
    const int wm   = wid & 1;          // 0..1  (m)
    const int wn   = wid >> 1;         // 0..3  (n)
    const int bm0  = blockIdx.y * 128;
    const int bn0  = blockIdx.x * 128;

    // A loader: row = tid>>2 (m), kc4 = (tid&3)*4 (k); two 64-row halves
    const int a_row = tid >> 2;
    const int a_kc4 = (tid & 3) * 4;
    // B loader: k = tid>>5, n4 = (tid&31)*4; two 8-row halves
    const int b_k  = tid >> 5;
    const int b_n4 = (tid & 31) * 4;

    const float* Ag = A + (size_t)(bm0 + a_row) * K + a_kc4;
    const float* Bg = B + (size_t)b_k * N + bn0 + b_n4;

    // ---- preload tile 0 ----
    {
        #pragma unroll
        for (int i = 0; i < 2; i++) {
            float4 av = *(const float4*)(Ag + (size_t)(i * 64) * K);
            const int r = a_row + i * 64;
            As[0][a_kc4 + 0][r] = f2tf32f(av.x);
            As[0][a_kc4 + 1][r] = f2tf32f(av.y);
            As[0][a_kc4 + 2][r] = f2tf32f(av.z);
            As[0][a_kc4 + 3][r] = f2tf32f(av.w);
            float4 bv = *(const float4*)(Bg + (size_t)(i * 8) * N);
            bv.x = f2tf32f(bv.x); bv.y = f2tf32f(bv.y);
            bv.z = f2tf32f(bv.z); bv.w = f2tf32f(bv.w);
            *(float4*)&Bs[0][b_k + i * 8][b_n4] = bv;
        }
    }
    __syncthreads();

    wmma::fragment<wmma::accumulator, 16, 16, 8, float> acc[4][2];
    #pragma unroll
    for (int mi = 0; mi < 4; mi++)
        #pragma unroll
        for (int ni = 0; ni < 2; ni++)
            wmma::fill_fragment(acc[mi][ni], 0.0f);

    const int m0 = wm * 64;
    const int n0 = wn * 32;
    const int niters = K >> 4;

    float4 pa[2], pb[2];
    for (int t = 0; t < niters; t++) {
        const int buf = t & 1;
        if (t + 1 < niters) {
            const int kt = (t + 1) * KSTEP;
            #pragma unroll
            for (int i = 0; i < 2; i++) {
                pa[i] = *(const float4*)(Ag + (size_t)(i * 64) * K + kt);
                pb[i] = *(const float4*)(Bg + (size_t)(kt + i * 8) * N);
            }
        }

        #pragma unroll
        for (int sub = 0; sub < 2; sub++) {
            const int kk = sub * 8;
            wmma::fragment<wmma::matrix_a, 16, 16, 8,
                           wmma::precision::tf32, wmma::col_major> afrag[4];
            wmma::fragment<wmma::matrix_b, 16, 16, 8,
                           wmma::precision::tf32, wmma::row_major> bfrag[2];
            #pragma unroll
            for (int mi = 0; mi < 4; mi++)
                wmma::load_matrix_sync(afrag[mi], &As[buf][kk][m0 + mi * 16], SSTR);
            #pragma unroll
            for (int ni = 0; ni < 2; ni++)
                wmma::load_matrix_sync(bfrag[ni], &Bs[buf][kk][n0 + ni * 16], SSTR);
            #pragma unroll
            for (int mi = 0; mi < 4; mi++)
                #pragma unroll
                for (int ni = 0; ni < 2; ni++)
                    wmma::mma_sync(acc[mi][ni], afrag[mi], bfrag[ni], acc[mi][ni]);
        }

        if (t + 1 < niters) {
            const int nb = buf ^ 1;
            #pragma unroll
            for (int i = 0; i < 2; i++) {
                const int r = a_row + i * 64;
                As[nb][a_kc4 + 0][r] = f2tf32f(pa[i].x);
                As[nb][a_kc4 + 1][r] = f2tf32f(pa[i].y);
                As[nb][a_kc4 + 2][r] = f2tf32f(pa[i].z);
                As[nb][a_kc4 + 3][r] = f2tf32f(pa[i].w);
                float4 bv = pb[i];
                bv.x = f2tf32f(bv.x); bv.y = f2tf32f(bv.y);
                bv.z = f2tf32f(bv.z); bv.w = f2tf32f(bv.w);
                *(float4*)&Bs[nb][b_k + i * 8][b_n4] = bv;
            }
        }
        __syncthreads();
    }

    // ---- epilogue: store fragments straight to global ----
    if (SPLIT_QKV) {
        // Tile cols bn0..bn0+127 lie in one (q/k/v, head) slice; rows in one b.
        const int which = bn0 >> 11;            // 0=q 1=k 2=v
        const int h     = (bn0 & 2047) >> 7;
        const int b     = bm0 >> 11;
        const int s0    = bm0 & 2047;
        float* dstb = (which == 0 ? C0 : (which == 1 ? C1 : C2))
                      + ((size_t)(b * HH + h) * SS) * DD;
        #pragma unroll
        for (int mi = 0; mi < 4; mi++) {
            #pragma unroll
            for (int ni = 0; ni < 2; ni++) {
                const int row = s0 + m0 + mi * 16;
                const int col = n0 + ni * 16;          // col == d
                wmma::store_matrix_sync(dstb + (size_t)row * DD + col,
                                        acc[mi][ni], DD, wmma::mem_row_major);
            }
        }
    } else {
        #pragma unroll
        for (int mi = 0; mi < 4; mi++) {
            #pragma unroll
            for (int ni = 0; ni < 2; ni++) {
                const int row = bm0 + m0 + mi * 16;
                const int col = bn0 + n0 + ni * 16;
                wmma::store_matrix_sync(C0 + (size_t)row * N + col,
                                        acc[mi][ni], N, wmma::mem_row_major);
            }
        }
    }
}

// ---------------------------------------------------------------------------
// RoPE + QK-RMSNorm, in-place on q,k in [B,H,S,D] layout.
// ---------------------------------------------------------------------------
__global__ __launch_bounds__(64)
void rope_norm(float* __restrict__ q, float* __restrict__ k)
{
    const int h = blockIdx.x;
    const int s = blockIdx.y;
    const int b = blockIdx.z;
    const int j = threadIdx.x;          // pair index 0..63

    const size_t base = ((size_t)((b * HH + h) * SS + s)) * DD + 2 * j;
    const float2 qp = *(const float2*)(q + base);
    const float2 kp = *(const float2*)(k + base);

    const float ex   = (float)(2 * j) * (1.0f / (float)DD);
    const float invf = 1.0f / powf(10000.0f, ex);
    const float fr   = (float)s * invf;
    float sn, cs;
    sincosf(fr, &sn, &cs);

    const float q0 = qp.x * cs - qp.y * sn;
    const float q1 = qp.x * sn + qp.y * cs;
    const float k0 = kp.x * cs - kp.y * sn;
    const float k1 = kp.x * sn + kp.y * cs;

    float sq = q0 * q0 + q1 * q1;
    float sk = k0 * k0 + k1 * k1;
    #pragma unroll
    for (int off = 16; off; off >>= 1) {
        sq += __shfl_xor_sync(0xffffffffu, sq, off);
        sk += __shfl_xor_sync(0xffffffffu, sk, off);
    }
    __shared__ float sh[4];
    if ((j & 31) == 0) { sh[(j >> 5) * 2] = sq; sh[(j >> 5) * 2 + 1] = sk; }
    __syncthreads();
    const float tq = sh[0] + sh[2];
    const float tk = sh[1] + sh[3];
    const float rq = rsqrtf(tq * (1.0f / (float)DD) + 1e-5f);
    const float rk = rsqrtf(tk * (1.0f / (float)DD) + 1e-5f);

    *(float2*)(q + base) = make_float2(q0 * rq, q1 * rq);
    *(float2*)(k + base) = make_float2(k0 * rk, k1 * rk);
}

// ---------------------------------------------------------------------------
// Causal flash attention, fp32, online softmax.
// Grid: (S/64, B*H). 256 threads = 16x16; 4x4 score microtile, 4x8 O microtile.
// ---------------------------------------------------------------------------
#define QS_STRIDE 68
#define PS_STRIDE 65
#define FLASH_SMEM_FLOATS (DD * QS_STRIDE * 2 + 64 * DD + 64 * PS_STRIDE)
#define FLASH_SMEM_BYTES  (FLASH_SMEM_FLOATS * 4)

__global__ __launch_bounds__(256)
void flash_attn(const float* __restrict__ Qg, const float* __restrict__ Kg,
                const float* __restrict__ Vg, float* __restrict__ Yg)
{
    const int bh  = blockIdx.y;
    const int qt  = blockIdx.x;
    const int qm0 = qt * 64;
    const int b   = bh >> 4;      // H = 16
    const int h   = bh & 15;

    extern __shared__ float sm[];
    float* Qs = sm;                      // [128][68] transposed
    float* Ks = Qs + DD * QS_STRIDE;     // [128][68] transposed
    float* Vs = Ks + DD * QS_STRIDE;     // [64][128]
    float* Ps = Vs + 64 * DD;            // [64][65]

    const int tid = threadIdx.x;
    const int tx  = tid & 15;
    const int ty  = tid >> 4;

    const float* Qb = Qg + (size_t)bh * SS * DD;
    const float* Kb = Kg + (size_t)bh * SS * DD;
    const float* Vb = Vg + (size_t)bh * SS * DD;

    for (int e = tid; e < 64 * 32; e += 256) {
        const int i  = e >> 5;
        const int d4 = (e & 31) << 2;
        float4 v = *(const float4*)(Qb + (size_t)(qm0 + i) * DD + d4);
        Qs[(d4 + 0) * QS_STRIDE + i] = v.x;
        Qs[(d4 + 1) * QS_STRIDE + i] = v.y;
        Qs[(d4 + 2) * QS_STRIDE + i] = v.z;
        Qs[(d4 + 3) * QS_STRIDE + i] = v.w;
    }

    float o[4][8];
    float m[4], l[4];
    #pragma unroll
    for (int ii = 0; ii < 4; ii++) {
        m[ii] = -1e30f; l[ii] = 0.0f;
        #pragma unroll
        for (int c = 0; c < 8; c++) o[ii][c] = 0.0f;
    }
    const float scale = 0.08838834764831845f;   // 1/sqrt(128)

    for (int kt = 0; kt <= qt; kt++) {
        const int kn0 = kt * 64;
        __syncthreads();

        for (int e = tid; e < 64 * 32; e += 256) {
            const int j  = e >> 5;
            const int d4 = (e & 31) << 2;
            float4 kv = *(const float4*)(Kb + (size_t)(kn0 + j) * DD + d4);
            Ks[(d4 + 0) * QS_STRIDE + j] = kv.x;
            Ks[(d4 + 1) * QS_STRIDE + j] = kv.y;
            Ks[(d4 + 2) * QS_STRIDE + j] = kv.z;
            Ks[(d4 + 3) * QS_STRIDE + j] = kv.w;
            *(float4*)&Vs[j * DD + d4] = *(const float4*)(Vb + (size_t)(kn0 + j) * DD + d4);
        }
        __syncthreads();

        float s[4][4];
        #pragma unroll
        for (int ii = 0; ii < 4; ii++)
            #pragma unroll
            for (int jj = 0; jj < 4; jj++) s[ii][jj] = 0.0f;

        #pragma unroll 8
        for (int d = 0; d < DD; d++) {
            float4 aq = *(float4*)&Qs[d * QS_STRIDE + ty * 4];
            float4 bk = *(float4*)&Ks[d * QS_STRIDE + tx * 4];
            const float a[4]  = {aq.x, aq.y, aq.z, aq.w};
            const float bb[4] = {bk.x, bk.y, bk.z, bk.w};
            #pragma unroll
            for (int ii = 0; ii < 4; ii++)
                #pragma unroll
                for (int jj = 0; jj < 4; jj++)
                    s[ii][jj] = fmaf(a[ii], bb[jj], s[ii][jj]);
        }

        #pragma unroll
        for (int ii = 0; ii < 4; ii++)
            #pragma unroll
            for (int jj = 0; jj < 4; jj++)
                s[ii][jj] *= scale;
        if (kt == qt) {
            #pragma unroll
            for (int ii = 0; ii < 4; ii++) {
                const int ig = ty * 4 + ii;
                #pragma unroll
                for (int jj = 0; jj < 4; jj++)
                    if (tx * 4 + jj > ig) s[ii][jj] = -1e30f;
            }
        }

        #pragma unroll
        for (int ii = 0; ii < 4; ii++) {
            float mx = fmaxf(fmaxf(s[ii][0], s[ii][1]), fmaxf(s[ii][2], s[ii][3]));
            #pragma unroll
            for (int off = 1; off < 16; off <<= 1)
                mx = fmaxf(mx, __shfl_xor_sync(0xffffffffu, mx, off));
            const float nm   = fmaxf(m[ii], mx);
            const float corr = __expf(m[ii] - nm);
            float rs = 0.0f;
            #pragma unroll
            for (int jj = 0; jj < 4; jj++) {
                const float p = __expf(s[ii][jj] - nm);
                s[ii][jj] = p;
                rs += p;
            }
            #pragma unroll
            for (int off = 1; off < 16; off <<= 1)
                rs += __shfl_xor_sync(0xffffffffu, rs, off);
            l[ii] = l[ii] * corr + rs;
            m[ii] = nm;
            #pragma unroll
            for (int c = 0; c < 8; c++) o[ii][c] *= corr;
            #pragma unroll
            for (int jj = 0; jj < 4; jj++)
                Ps[(ty * 4 + ii) * PS_STRIDE + tx * 4 + jj] = s[ii][jj];
        }
        __syncthreads();

        #pragma unroll 4
        for (int j = 0; j < 64; j++) {
            float4 b0 = *(float4*)&Vs[j * DD + tx * 8];
            float4 b1 = *(float4*)&Vs[j * DD + tx * 8 + 4];
            float a[4];
            #pragma unroll
            for (int ii = 0; ii < 4; ii++) a[ii] = Ps[(ty * 4 + ii) * PS_STRIDE + j];
            #pragma unroll
            for (int ii = 0; ii < 4; ii++) {
                o[ii][0] = fmaf(a[ii], b0.x, o[ii][0]);
                o[ii][1] = fmaf(a[ii], b0.y, o[ii][1]);
                o[ii][2] = fmaf(a[ii], b0.z, o[ii][2]);
                o[ii][3] = fmaf(a[ii], b0.w, o[ii][3]);
                o[ii][4] = fmaf(a[ii], b1.x, o[ii][4]);
                o[ii][5] = fmaf(a[ii], b1.y, o[ii][5]);
                o[ii][6] = fmaf(a[ii], b1.z, o[ii][6]);
                o[ii][7] = fmaf(a[ii], b1.w, o[ii][7]);
            }
        }
    }

    #pragma unroll
    for (int ii = 0; ii < 4; ii++) {
        const float invl = 1.0f / l[ii];
        const int ig = qm0 + ty * 4 + ii;
        float* yp = Yg + ((size_t)(b * SS + ig)) * EE + h * DD + tx * 8;
        *(float4*)yp       = make_float4(o[ii][0] * invl, o[ii][1] * invl,
                                         o[ii][2] * invl, o[ii][3] * invl);
        *(float4*)(yp + 4) = make_float4(o[ii][4] * invl, o[ii][5] * invl,
                                         o[ii][6] * invl, o[ii][7] * invl);
    }
}

// ---------------------------------------------------------------------------
// Launch
// ---------------------------------------------------------------------------
extern "C" void kernel_launch(void* const* d_in, const int* in_sizes, int n_in,
                              void* d_out, int out_size)
{
    const float* x      = (const float*)d_in[0];
    const float* w_qkv  = (const float*)d_in[1];
    const float* w_proj = (const float*)d_in[2];
    float* out          = (float*)d_out;

    float *q_p, *k_p, *v_p, *y_p;
    cudaGetSymbolAddress((void**)&q_p, g_q);
    cudaGetSymbolAddress((void**)&k_p, g_k);
    cudaGetSymbolAddress((void**)&v_p, g_v);
    cudaGetSymbolAddress((void**)&y_p, g_y);

    cudaFuncSetAttribute(flash_attn, cudaFuncAttributeMaxDynamicSharedMemorySize,
                         FLASH_SMEM_BYTES);

    // 1) QKV projection (tf32 wmma) with fused head-split
    gemm_tf32<1><<<dim3(QKVN / 128, MM / 128), 256>>>(x, w_qkv, q_p, k_p, v_p,
                                                      MM, QKVN, EE);

    // 2) RoPE + RMSNorm in-place on q,k
    rope_norm<<<dim3(HH, SS, BB), 64>>>(q_p, k_p);

    // 3) Causal flash attention (fp32)
    flash_attn<<<dim3(SS / 64, BB * HH), 256, FLASH_SMEM_BYTES>>>(q_p, k_p, v_p, y_p);

    // 4) Output projection (tf32 wmma)
    gemm_tf32<0><<<dim3(EE / 128, MM / 128), 256>>>(y_p, w_proj, out, nullptr, nullptr,
                                                    MM, EE, EE);
}